// round 3
// baseline (speedup 1.0000x reference)
#include <cuda_runtime.h>

// Problem shape (fixed)
#define BB 4096
#define GG 100
#define TT 24
#define TX 12            // t-pairs per (b)
#define NCH 16           // chunk-threads per (b,t-pair)
#define CH 7             // entries per chunk: 16*7 = 112 >= 101
#define PADN (NCH*CH)    // 112
#define NBZ 2            // b's per block -> blockDim (12,16,2) = 384

// ---------------------------------------------------------------------------
// Single fused kernel: per-block stable rank-sort of the 101 prices (tiny),
// then parallel prefix-sum greedy dispatch with float2 vectorization over t.
// desc.x: byte offset g*TT*4 for generators, -1 = slack, -2 = pad.
// desc.y: price bits.
// ---------------------------------------------------------------------------
__global__ __launch_bounds__(TX * NCH * NBZ)
void dispatch_kernel(const float* __restrict__ R_up,
                     const float* __restrict__ R_dn,
                     const float* __restrict__ omega,
                     const float* __restrict__ b_G,
                     const float* __restrict__ voll,
                     const float* __restrict__ vosp,
                     const float* __restrict__ rt_up_ratio,
                     const float* __restrict__ rt_dn_ratio,
                     float* __restrict__ du,
                     float* __restrict__ dd,
                     float* __restrict__ LS,
                     float* __restrict__ SP,
                     float* __restrict__ rt_obj) {
    __shared__ float  s_p[2][GG + 1];
    __shared__ int2   s_desc[2][PADN];
    __shared__ float2 s_sum[2][NBZ][NCH][TX];
    __shared__ float2 s_cost[NBZ][NCH][TX];

    const int tx  = threadIdx.x;  // t-pair
    const int ty  = threadIdx.y;  // chunk
    const int tz  = threadIdx.z;  // local b
    const int tid = tx + TX * (ty + NCH * tz);

    // ---- in-block merit-order sort (stable argsort of 101 prices) ----
    if (tid <= GG) {
        float bg = (tid < GG) ? b_G[tid] : 0.0f;
        s_p[0][tid] = (tid < GG) ? (*rt_up_ratio) * bg : *voll;
        s_p[1][tid] = (tid < GG) ? (*rt_dn_ratio) * bg : *vosp;
    }
    __syncthreads();
    if (tid <= GG) {
        #pragma unroll
        for (int dir = 0; dir < 2; ++dir) {
            float pi = s_p[dir][tid];
            int rank = 0;
            for (int j = 0; j <= GG; ++j) {
                float pj = s_p[dir][j];
                rank += (pj < pi) || (pj == pi && j < tid);
            }
            int off = (tid < GG) ? tid * TT * 4 : -1;
            s_desc[dir][rank] = make_int2(off, __float_as_int(pi));
        }
    } else if (tid < PADN) {
        s_desc[0][tid] = make_int2(-2, 0);
        s_desc[1][tid] = make_int2(-2, 0);
    }
    __syncthreads();

    // ---- per-(b, t-pair, chunk) greedy dispatch ----
    const int b  = blockIdx.x * NBZ + tz;
    const int t2 = 2 * tx;
    const size_t base = (size_t)b * (GG * TT) + t2;

    const char* RuB = (const char*)(R_up + base);
    const char* RdB = (const char*)(R_dn + base);
    char* DuB = (char*)(du + base);
    char* DdB = (char*)(dd + base);

    const float2 w = *(const float2*)(omega + b * TT + t2);
    const float2 dem_u = make_float2(fmaxf(w.x, 0.0f), fmaxf(w.y, 0.0f));
    const float2 dem_d = make_float2(fmaxf(-w.x, 0.0f), fmaxf(-w.y, 0.0f));

    const int gi0 = ty * CH;

    // Phase 1: caps into registers, local chunk sums.
    float2 cu[CH], cd[CH];
    float2 su = make_float2(0.0f, 0.0f), sd = make_float2(0.0f, 0.0f);
    #pragma unroll
    for (int i = 0; i < CH; ++i) {
        int2 d = s_desc[0][gi0 + i];
        float2 c;
        if (d.x >= 0)       c = *(const float2*)(RuB + d.x);
        else if (d.x == -1) c = dem_u;
        else                c = make_float2(0.0f, 0.0f);
        cu[i] = c;  su.x += c.x;  su.y += c.y;

        d = s_desc[1][gi0 + i];
        if (d.x >= 0)       c = *(const float2*)(RdB + d.x);
        else if (d.x == -1) c = dem_d;
        else                c = make_float2(0.0f, 0.0f);
        cd[i] = c;  sd.x += c.x;  sd.y += c.y;
    }

    s_sum[0][tz][ty][tx] = su;
    s_sum[1][tz][ty][tx] = sd;
    __syncthreads();

    // Exclusive prefix over chunk sums.
    float2 run_u = make_float2(0.0f, 0.0f), run_d = make_float2(0.0f, 0.0f);
    #pragma unroll
    for (int c = 0; c < NCH; ++c) {
        if (c < ty) {
            float2 a = s_sum[0][tz][c][tx];
            float2 e = s_sum[1][tz][c][tx];
            run_u.x += a.x;  run_u.y += a.y;
            run_d.x += e.x;  run_d.y += e.y;
        }
    }

    // Phase 2: alloc = clip(dem - before, 0, cap); stores + cost.
    float2 cost = make_float2(0.0f, 0.0f);
    #pragma unroll
    for (int i = 0; i < CH; ++i) {
        {
            int2 d = s_desc[0][gi0 + i];
            float p = __int_as_float(d.y);
            float2 a;
            a.x = fminf(fmaxf(dem_u.x - run_u.x, 0.0f), cu[i].x);
            a.y = fminf(fmaxf(dem_u.y - run_u.y, 0.0f), cu[i].y);
            run_u.x += cu[i].x;  run_u.y += cu[i].y;
            cost.x = fmaf(p, a.x, cost.x);
            cost.y = fmaf(p, a.y, cost.y);
            if (d.x >= 0)       *(float2*)(DuB + d.x) = a;
            else if (d.x == -1) *(float2*)(LS + b * TT + t2) = a;
        }
        {
            int2 d = s_desc[1][gi0 + i];
            float p = __int_as_float(d.y);
            float2 a;
            a.x = fminf(fmaxf(dem_d.x - run_d.x, 0.0f), cd[i].x);
            a.y = fminf(fmaxf(dem_d.y - run_d.y, 0.0f), cd[i].y);
            run_d.x += cd[i].x;  run_d.y += cd[i].y;
            cost.x = fmaf(p, a.x, cost.x);
            cost.y = fmaf(p, a.y, cost.y);
            if (d.x >= 0)       *(float2*)(DdB + d.x) = a;
            else if (d.x == -1) *(float2*)(SP + b * TT + t2) = a;
        }
    }

    // Deterministic cost reduction: chunks, then t, per b.
    s_cost[tz][ty][tx] = cost;
    __syncthreads();
    if (ty == 0) {
        float2 s = make_float2(0.0f, 0.0f);
        #pragma unroll
        for (int c = 0; c < NCH; ++c) {
            float2 v = s_cost[tz][c][tx];
            s.x += v.x;  s.y += v.y;
        }
        s_cost[tz][0][tx] = s;
    }
    __syncthreads();
    if (ty == 0 && tx == 0) {
        float s = 0.0f;
        #pragma unroll
        for (int t = 0; t < TX; ++t) {
            float2 v = s_cost[tz][0][t];
            s += v.x + v.y;
        }
        rt_obj[b] = s;
    }
}

extern "C" void kernel_launch(void* const* d_in, const int* in_sizes, int n_in,
                              void* d_out, int out_size) {
    const float* R_up        = (const float*)d_in[0];
    const float* R_dn        = (const float*)d_in[1];
    const float* omega_true  = (const float*)d_in[2];
    const float* b_G         = (const float*)d_in[3];
    const float* voll        = (const float*)d_in[4];
    const float* vosp        = (const float*)d_in[5];
    const float* rt_up_ratio = (const float*)d_in[6];
    const float* rt_dn_ratio = (const float*)d_in[7];

    float* out = (float*)d_out;
    float* du  = out;
    float* dd  = du + (size_t)BB * GG * TT;
    float* LS  = dd + (size_t)BB * GG * TT;
    float* SP  = LS + (size_t)BB * TT;
    float* rt  = SP + (size_t)BB * TT;

    dim3 block(TX, NCH, NBZ);
    dim3 grid(BB / NBZ);
    dispatch_kernel<<<grid, block>>>(R_up, R_dn, omega_true, b_G,
                                     voll, vosp, rt_up_ratio, rt_dn_ratio,
                                     du, dd, LS, SP, rt);
}

// round 4
// speedup vs baseline: 1.2762x; 1.2762x over previous
#include <cuda_runtime.h>

// Problem shape (fixed)
#define BB 4096
#define GG 100
#define TT 24
#define TX 12            // t-pairs (float2 over t)
#define NCH 16           // chunk-threads per (b, t-pair)
#define CH 7             // entries per chunk: 16*7 = 112 >= 101
#define PADN (NCH*CH)    // 112
#define NBZ 2            // b's per block -> blockDim (12,16,2) = 384

// Packed sorted descriptors: .x = byte offset g*TT*4 (generator), -1 = slack,
// -2 = pad; .y = price bits. [0]=up, [1]=dn.
__device__ int2 g_desc[2][PADN];

// ---------------------------------------------------------------------------
// Setup: stable argsort of 101 prices per direction, one tiny block.
// ---------------------------------------------------------------------------
__global__ void setup_kernel(const float* __restrict__ b_G,
                             const float* __restrict__ voll,
                             const float* __restrict__ vosp,
                             const float* __restrict__ rt_up_ratio,
                             const float* __restrict__ rt_dn_ratio) {
    __shared__ float p[2][GG + 1];
    int i = threadIdx.x;
    if (i <= GG) {
        float bg = (i < GG) ? b_G[i] : 0.0f;
        p[0][i] = (i < GG) ? (*rt_up_ratio) * bg : *voll;
        p[1][i] = (i < GG) ? (*rt_dn_ratio) * bg : *vosp;
    }
    __syncthreads();
    if (i <= GG) {
        #pragma unroll
        for (int dir = 0; dir < 2; ++dir) {
            float pi = p[dir][i];
            int rank = 0;
            for (int j = 0; j <= GG; ++j) {
                float pj = p[dir][j];
                rank += (pj < pi) || (pj == pi && j < i);
            }
            int off = (i < GG) ? i * TT * 4 : -1;
            g_desc[dir][rank] = make_int2(off, __float_as_int(pi));
        }
    } else if (i - (GG + 1) < PADN - (GG + 1)) {
        int k = GG + 1 + (i - (GG + 1));   // 101..111
        if (k < PADN) {
            g_desc[0][k] = make_int2(-2, 0);
            g_desc[1][k] = make_int2(-2, 0);
        }
    }
}

// ---------------------------------------------------------------------------
// Main: 16 chunk-threads per (b, t-pair). Prefix-sum greedy dispatch, float2.
// ---------------------------------------------------------------------------
__global__ __launch_bounds__(TX * NCH * NBZ)
void dispatch_kernel(const float* __restrict__ R_up,
                     const float* __restrict__ R_dn,
                     const float* __restrict__ omega,
                     float* __restrict__ du,
                     float* __restrict__ dd,
                     float* __restrict__ LS,
                     float* __restrict__ SP,
                     float* __restrict__ rt_obj) {
    __shared__ int2   s_desc[2][PADN];
    __shared__ float2 s_sum[2][NBZ][NCH][TX];
    __shared__ float2 s_cost[NBZ][NCH][TX];

    const int tx  = threadIdx.x;  // t-pair
    const int ty  = threadIdx.y;  // chunk
    const int tz  = threadIdx.z;  // local b
    const int tid = tx + TX * (ty + NCH * tz);

    if (tid < PADN) {
        s_desc[0][tid] = g_desc[0][tid];
        s_desc[1][tid] = g_desc[1][tid];
    }
    __syncthreads();

    const int b  = blockIdx.x * NBZ + tz;
    const int t2 = 2 * tx;
    const size_t base = (size_t)b * (GG * TT) + t2;

    const char* RuB = (const char*)(R_up + base);
    const char* RdB = (const char*)(R_dn + base);
    char* DuB = (char*)(du + base);
    char* DdB = (char*)(dd + base);

    const float2 w = *(const float2*)(omega + b * TT + t2);
    const float2 dem_u = make_float2(fmaxf(w.x, 0.0f), fmaxf(w.y, 0.0f));
    const float2 dem_d = make_float2(fmaxf(-w.x, 0.0f), fmaxf(-w.y, 0.0f));

    const int gi0 = ty * CH;

    // Phase 1: caps into registers (MLP), local chunk sums.
    float2 cu[CH], cd[CH];
    float2 su = make_float2(0.0f, 0.0f), sd = make_float2(0.0f, 0.0f);
    #pragma unroll
    for (int i = 0; i < CH; ++i) {
        int2 d = s_desc[0][gi0 + i];
        float2 c;
        if (d.x >= 0)       c = *(const float2*)(RuB + d.x);
        else if (d.x == -1) c = dem_u;
        else                c = make_float2(0.0f, 0.0f);
        cu[i] = c;  su.x += c.x;  su.y += c.y;

        d = s_desc[1][gi0 + i];
        if (d.x >= 0)       c = *(const float2*)(RdB + d.x);
        else if (d.x == -1) c = dem_d;
        else                c = make_float2(0.0f, 0.0f);
        cd[i] = c;  sd.x += c.x;  sd.y += c.y;
    }

    s_sum[0][tz][ty][tx] = su;
    s_sum[1][tz][ty][tx] = sd;
    __syncthreads();

    // Exclusive prefix over chunk sums (ascending chunk = ascending rank).
    float2 run_u = make_float2(0.0f, 0.0f), run_d = make_float2(0.0f, 0.0f);
    #pragma unroll
    for (int c = 0; c < NCH; ++c) {
        if (c < ty) {
            float2 a = s_sum[0][tz][c][tx];
            float2 e = s_sum[1][tz][c][tx];
            run_u.x += a.x;  run_u.y += a.y;
            run_d.x += e.x;  run_d.y += e.y;
        }
    }

    // Phase 2: alloc = clip(dem - before, 0, cap); stores + cost.
    float2 cost = make_float2(0.0f, 0.0f);
    #pragma unroll
    for (int i = 0; i < CH; ++i) {
        {
            int2 d = s_desc[0][gi0 + i];
            float p = __int_as_float(d.y);
            float2 a;
            a.x = fminf(fmaxf(dem_u.x - run_u.x, 0.0f), cu[i].x);
            a.y = fminf(fmaxf(dem_u.y - run_u.y, 0.0f), cu[i].y);
            run_u.x += cu[i].x;  run_u.y += cu[i].y;
            cost.x = fmaf(p, a.x, cost.x);
            cost.y = fmaf(p, a.y, cost.y);
            if (d.x >= 0)       *(float2*)(DuB + d.x) = a;
            else if (d.x == -1) *(float2*)(LS + b * TT + t2) = a;
        }
        {
            int2 d = s_desc[1][gi0 + i];
            float p = __int_as_float(d.y);
            float2 a;
            a.x = fminf(fmaxf(dem_d.x - run_d.x, 0.0f), cd[i].x);
            a.y = fminf(fmaxf(dem_d.y - run_d.y, 0.0f), cd[i].y);
            run_d.x += cd[i].x;  run_d.y += cd[i].y;
            cost.x = fmaf(p, a.x, cost.x);
            cost.y = fmaf(p, a.y, cost.y);
            if (d.x >= 0)       *(float2*)(DdB + d.x) = a;
            else if (d.x == -1) *(float2*)(SP + b * TT + t2) = a;
        }
    }

    // Deterministic cost reduction: chunks, then t, per b.
    s_cost[tz][ty][tx] = cost;
    __syncthreads();
    if (ty == 0) {
        float2 s = make_float2(0.0f, 0.0f);
        #pragma unroll
        for (int c = 0; c < NCH; ++c) {
            float2 v = s_cost[tz][c][tx];
            s.x += v.x;  s.y += v.y;
        }
        s_cost[tz][0][tx] = s;
    }
    __syncthreads();
    if (ty == 0 && tx == 0) {
        float s = 0.0f;
        #pragma unroll
        for (int t = 0; t < TX; ++t) {
            float2 v = s_cost[tz][0][t];
            s += v.x + v.y;
        }
        rt_obj[b] = s;
    }
}

extern "C" void kernel_launch(void* const* d_in, const int* in_sizes, int n_in,
                              void* d_out, int out_size) {
    const float* R_up        = (const float*)d_in[0];
    const float* R_dn        = (const float*)d_in[1];
    const float* omega_true  = (const float*)d_in[2];
    const float* b_G         = (const float*)d_in[3];
    const float* voll        = (const float*)d_in[4];
    const float* vosp        = (const float*)d_in[5];
    const float* rt_up_ratio = (const float*)d_in[6];
    const float* rt_dn_ratio = (const float*)d_in[7];

    float* out = (float*)d_out;
    float* du  = out;
    float* dd  = du + (size_t)BB * GG * TT;
    float* LS  = dd + (size_t)BB * GG * TT;
    float* SP  = LS + (size_t)BB * TT;
    float* rt  = SP + (size_t)BB * TT;

    setup_kernel<<<1, 128>>>(b_G, voll, vosp, rt_up_ratio, rt_dn_ratio);

    dim3 block(TX, NCH, NBZ);
    dim3 grid(BB / NBZ);
    dispatch_kernel<<<grid, block>>>(R_up, R_dn, omega_true, du, dd, LS, SP, rt);
}